// round 1
// baseline (speedup 1.0000x reference)
#include <cuda_runtime.h>
#include <cstdint>

namespace {

constexpr int B_  = 2;
constexpr int T_  = 5;
constexpr int C_  = 3;
constexpr int H_  = 96;
constexpr int W_  = 96;
constexpr int S0_ = 4;
constexpr int NH_ = H_ / S0_;            // 24
constexpr int NW_ = W_ / S0_;            // 24
constexpr int Q_  = T_ * NH_ * NW_;      // 2880
constexpr int L_  = 243;                 // (2*WT+1) * WS * WS = 3*9*9
constexpr int K_  = 10;
constexpr int LSELF = 121;               // WT*WS*WS + r*WS + r
constexpr int HW_   = H_ * W_;
constexpr int CHW_  = C_ * HW_;
constexpr int TCHW_ = T_ * CHW_;
constexpr float INV_DEN = 1.0f / (float)(B_ * Q_ * (K_ - 1));   // 1/51840

__device__ __forceinline__ int refl(int i, int n) {
    i = (i < 0) ? -i : i;
    return (i >= n) ? (2 * (n - 1) - i) : i;
}
__device__ __forceinline__ int clampi(int v, int lo, int hi) {
    return v < lo ? lo : (v > hi ? hi : v);
}
__device__ __forceinline__ unsigned long long umin64(unsigned long long a, unsigned long long b) {
    return a < b ? a : b;
}

__global__ void init_out_kernel(float* out) {
    out[0] = 0.0f;
}

__global__ __launch_bounds__(256, 8)
void dnls_loss_kernel(const float* __restrict__ noisy,
                      const float* __restrict__ deno,
                      float* __restrict__ out)
{
    const int bq = blockIdx.x;
    const int b  = bq / Q_;
    const int q  = bq - b * Q_;
    const int qt = q / (NH_ * NW_);
    const int rem = q - qt * (NH_ * NW_);
    const int qh = (rem / NW_) * S0_;
    const int qw = (rem - (rem / NW_) * NW_) * S0_;

    const int tid = threadIdx.x;

    const float* nb = noisy + (size_t)b * TCHW_;
    const float* db = deno  + (size_t)b * TCHW_;

    __shared__ float qpatch[75];        // 5x5x3 query patch (noisy)
    __shared__ float denoQ[147];        // 7x7x3 query patch (deno)
    __shared__ unsigned long long warpmin[8];
    __shared__ unsigned long long bestk;
    __shared__ int sel_l[K_];
    __shared__ float wsum[8];

    // ---- Stage query patches into SMEM ----
    if (tid < 75) {
        int c = tid / 25;
        int p = tid - c * 25;
        int ph = p / 5, pw = p - (p / 5) * 5;
        int hh = refl(qh + ph - 2, H_);
        int ww = refl(qw + pw - 2, W_);
        qpatch[tid] = nb[(qt * C_ + c) * HW_ + hh * W_ + ww];
    }
    if (tid < 147) {
        int c = tid / 49;
        int p = tid - c * 49;
        int ph = p / 7, pw = p - (p / 7) * 7;
        int hh = refl(qh + ph - 3, H_);
        int ww = refl(qw + pw - 3, W_);
        denoQ[tid] = db[(qt * C_ + c) * HW_ + hh * W_ + ww];
    }
    __syncthreads();

    // ---- Phase A: candidate distances (thread l handles candidate l) ----
    unsigned long long mykey = 0xFFFFFFFFFFFFFFFFULL;
    if (tid < L_) {
        int dt = tid / 81 - 1;
        int r9 = (tid / 9) % 9;
        int dh = r9 - 4;
        int dw = (tid % 9) - 4;
        int ct = clampi(qt + dt, 0, T_ - 1);
        int ch = clampi(qh + dh, 0, H_ - 1);
        int cw = clampi(qw + dw, 0, W_ - 1);

        float d;
        if (tid == LSELF) {
            d = -1.0f;
        } else {
            d = 0.0f;
            #pragma unroll
            for (int c = 0; c < C_; c++) {
                #pragma unroll
                for (int ph = 0; ph < 5; ph++) {
                    int hh = refl(ch + ph - 2, H_);
                    const float* row = nb + (ct * C_ + c) * HW_ + hh * W_;
                    #pragma unroll
                    for (int pw = 0; pw < 5; pw++) {
                        int ww = refl(cw + pw - 2, W_);
                        float diff = qpatch[(c * 5 + ph) * 5 + pw] - __ldg(row + ww);
                        d = fmaf(diff, diff, d);
                    }
                }
            }
        }
        // Monotone float->uint mapping; low 32 bits = candidate index (tie-break: smaller l).
        unsigned int fb = __float_as_uint(d);
        fb = (fb & 0x80000000u) ? ~fb : (fb | 0x80000000u);
        mykey = ((unsigned long long)fb << 32) | (unsigned int)tid;
    }

    // ---- Phase B: iterative top-K (min key = min distance, min index) ----
    unsigned long long key = mykey;
    for (int k = 0; k < K_; k++) {
        unsigned long long v = key;
        #pragma unroll
        for (int off = 16; off; off >>= 1)
            v = umin64(v, __shfl_down_sync(0xFFFFFFFFu, v, off));
        if ((tid & 31) == 0) warpmin[tid >> 5] = v;
        __syncthreads();
        if (tid == 0) {
            unsigned long long m = warpmin[0];
            #pragma unroll
            for (int i = 1; i < 8; i++) m = umin64(m, warpmin[i]);
            bestk = m;
            sel_l[k] = (int)(m & 0xFFFFFFFFu);
        }
        __syncthreads();
        if (key == bestk) key = 0xFFFFFFFFFFFFFFFFULL;   // unique owner (low bits = l)
    }
    __syncthreads();

    // ---- Phase C: refined 7x7 distances for ranks 1..K-1 ----
    float acc = 0.0f;
    for (int j = tid; j < (K_ - 1) * 147; j += 256) {
        int kk  = j / 147;               // 0..8 -> ranks 1..9
        int dim = j - kk * 147;
        int l   = sel_l[kk + 1];
        int dt = l / 81 - 1;
        int dh = ((l / 9) % 9) - 4;
        int dw = (l % 9) - 4;
        int it = clampi(qt + dt, 0, T_ - 1);
        int ih = clampi(qh + dh, 0, H_ - 1);
        int iw = clampi(qw + dw, 0, W_ - 1);
        int c  = dim / 49;
        int p  = dim - c * 49;
        int ph = p / 7, pw = p - (p / 7) * 7;
        int hh = refl(ih + ph - 3, H_);
        int ww = refl(iw + pw - 3, W_);
        float diff = denoQ[dim] - __ldg(nb + (it * C_ + c) * HW_ + hh * W_ + ww);
        acc = fmaf(diff, diff, acc);
    }

    // ---- Block reduce + single atomic per CTA ----
    #pragma unroll
    for (int off = 16; off; off >>= 1)
        acc += __shfl_down_sync(0xFFFFFFFFu, acc, off);
    if ((tid & 31) == 0) wsum[tid >> 5] = acc;
    __syncthreads();
    if (tid == 0) {
        float s = 0.0f;
        #pragma unroll
        for (int i = 0; i < 8; i++) s += wsum[i];
        atomicAdd(out, s * INV_DEN);
    }
}

}  // namespace

extern "C" void kernel_launch(void* const* d_in, const int* in_sizes, int n_in,
                              void* d_out, int out_size)
{
    const float* noisy = (const float*)d_in[0];
    const float* deno  = (const float*)d_in[1];
    float* out = (float*)d_out;

    init_out_kernel<<<1, 1>>>(out);
    dnls_loss_kernel<<<B_ * Q_, 256>>>(noisy, deno, out);
}

// round 6
// speedup vs baseline: 1.7720x; 1.7720x over previous
#include <cuda_runtime.h>
#include <cstdint>

namespace {

constexpr int B_  = 2;
constexpr int T_  = 5;
constexpr int C_  = 3;
constexpr int H_  = 96;
constexpr int W_  = 96;
constexpr int S0_ = 4;
constexpr int NH_ = H_ / S0_;            // 24
constexpr int NW_ = W_ / S0_;            // 24
constexpr int Q_  = T_ * NH_ * NW_;      // 2880
constexpr int L_  = 243;                 // 3 * 9 * 9
constexpr int K_  = 10;
constexpr int LSELF = 121;
constexpr int HW_   = H_ * W_;
constexpr int CHW_  = C_ * HW_;
constexpr int TCHW_ = T_ * CHW_;
constexpr float INV_DEN = 1.0f / (float)(B_ * Q_ * (K_ - 1));   // 1/51840

constexpr int TR = 15;   // tile rows/cols
constexpr int TS = 17;   // padded col stride (floats)

__device__ __forceinline__ int refl(int i, int n) {
    i = (i < 0) ? -i : i;
    return (i >= n) ? (2 * (n - 1) - i) : i;
}
__device__ __forceinline__ int clampi(int v, int lo, int hi) {
    return v < lo ? lo : (v > hi ? hi : v);
}
__device__ __forceinline__ unsigned long long umin64(unsigned long long a, unsigned long long b) {
    return a < b ? a : b;
}

__global__ void init_out_kernel(float* out) { out[0] = 0.0f; }

__global__ __launch_bounds__(256, 6)
void dnls_loss_kernel(const float* __restrict__ noisy,
                      const float* __restrict__ deno,
                      float* __restrict__ out)
{
    const int bq = blockIdx.x;
    const int b  = bq / Q_;
    const int q  = bq - b * Q_;
    const int qt = q / (NH_ * NW_);
    const int rem = q - qt * (NH_ * NW_);
    const int qh = (rem / NW_) * S0_;
    const int qw = (rem - (rem / NW_) * NW_) * S0_;

    const int tid = threadIdx.x;

    const float* nb = noisy + (size_t)b * TCHW_;
    const float* db = deno  + (size_t)b * TCHW_;

    __shared__ float tile[3][3][TR][TS];       // noisy crop: frame slot (dt+1) x chan x 15 x 15
    __shared__ float denoQ[147];               // 7x7x3 deno query patch
    __shared__ unsigned long long keys[256];
    __shared__ int sel_l[K_ - 1];              // ranks 1..9
    __shared__ float wsum[8];

    const int rlo = clampi(qh - 7, 0, H_ - TR);
    const int wlo = clampi(qw - 7, 0, W_ - TR);

    // ---- Stage tile: contiguous crop, fully in-bounds, no reflect needed ----
    for (int i = tid; i < 3 * 3 * TR * TR; i += 256) {
        int f  = i / (3 * TR * TR);
        int r0 = i - f * (3 * TR * TR);
        int c  = r0 / (TR * TR);     r0 -= c * (TR * TR);
        int r  = r0 / TR;
        int cl = r0 - r * TR;
        int gt = clampi(qt - 1 + f, 0, T_ - 1);
        tile[f][c][r][cl] = __ldg(nb + (gt * C_ + c) * HW_ + (rlo + r) * W_ + (wlo + cl));
    }
    if (tid < 147) {
        int c = tid / 49;
        int p = tid - c * 49;
        int ph = p / 7, pw = p - (p / 7) * 7;
        denoQ[tid] = __ldg(db + (qt * C_ + c) * HW_ + refl(qh + ph - 3, H_) * W_ + refl(qw + pw - 3, W_));
    }
    __syncthreads();

    // ---- Phase A: candidate distances from SMEM tile ----
    unsigned long long mykey = 0xFFFFFFFFFFFFFFFFULL;
    if (tid < L_ && tid != LSELF) {
        const int dt = tid / 81 - 1;
        const int dh = ((tid / 9) % 9) - 4;
        const int dw = (tid % 9) - 4;
        const int ch = clampi(qh + dh, 0, H_ - 1);
        const int cw = clampi(qw + dw, 0, W_ - 1);
        const int f  = dt + 1;

        int rIdx[5], cIdx[5], qrI[5], qcI[5];
        #pragma unroll
        for (int p = 0; p < 5; p++) {
            rIdx[p] = refl(ch + p - 2, H_) - rlo;
            cIdx[p] = refl(cw + p - 2, W_) - wlo;
            qrI[p]  = refl(qh + p - 2, H_) - rlo;   // uniform across block
            qcI[p]  = refl(qw + p - 2, W_) - wlo;
        }

        float d = 0.0f;
        #pragma unroll
        for (int c = 0; c < C_; c++) {
            #pragma unroll
            for (int ph = 0; ph < 5; ph++) {
                const float* trow = tile[f][c][rIdx[ph]];
                const float* qrow = tile[1][c][qrI[ph]];
                #pragma unroll
                for (int pw = 0; pw < 5; pw++) {
                    float diff = qrow[qcI[pw]] - trow[cIdx[pw]];
                    d = fmaf(diff, diff, d);
                }
            }
        }
        unsigned int fb = __float_as_uint(d);
        fb = (fb & 0x80000000u) ? ~fb : (fb | 0x80000000u);
        mykey = ((unsigned long long)fb << 32) | (unsigned int)tid;
    }
    keys[tid] = mykey;
    __syncthreads();

    // ---- Phase B: warp 0 selects 9 smallest (self rank-0 is implicit) ----
    if (tid < 32) {
        unsigned long long r[8];
        #pragma unroll
        for (int j = 0; j < 8; j++) r[j] = keys[tid + 32 * j];
        #pragma unroll
        for (int k = 0; k < K_ - 1; k++) {
            unsigned long long m = r[0];
            #pragma unroll
            for (int j = 1; j < 8; j++) m = umin64(m, r[j]);
            #pragma unroll
            for (int off = 16; off; off >>= 1)
                m = umin64(m, __shfl_xor_sync(0xFFFFFFFFu, m, off));
            if (tid == 0) sel_l[k] = (int)(m & 0xFFFFFFFFu);
            #pragma unroll
            for (int j = 0; j < 8; j++)
                if (r[j] == m) r[j] = 0xFFFFFFFFFFFFFFFFULL;
        }
    }
    __syncthreads();

    // ---- Phase C: refined 7x7x3 SSD for ranks 1..9, from the same tile ----
    float acc = 0.0f;
    if (tid < 252) {
        const int kk = tid / 28;                 // neighbor rank 1..9 (index 0..8)
        const int s0 = tid - kk * 28;
        const int l  = sel_l[kk];
        const int dt = l / 81 - 1;
        const int dh = ((l / 9) % 9) - 4;
        const int dw = (l % 9) - 4;
        const int ih = clampi(qh + dh, 0, H_ - 1);
        const int iw = clampi(qw + dw, 0, W_ - 1);
        const int f  = dt + 1;

        for (int dim = s0; dim < 147; dim += 28) {
            int c = dim / 49;
            int p = dim - c * 49;
            int ph = p / 7, pw = p - (p / 7) * 7;
            int rr = refl(ih + ph - 3, H_) - rlo;
            int cc = refl(iw + pw - 3, W_) - wlo;
            float diff = denoQ[dim] - tile[f][c][rr][cc];
            acc = fmaf(diff, diff, acc);
        }
    }

    // ---- Block reduce + one atomic per CTA ----
    #pragma unroll
    for (int off = 16; off; off >>= 1)
        acc += __shfl_down_sync(0xFFFFFFFFu, acc, off);
    if ((tid & 31) == 0) wsum[tid >> 5] = acc;
    __syncthreads();
    if (tid == 0) {
        float s = 0.0f;
        #pragma unroll
        for (int i = 0; i < 8; i++) s += wsum[i];
        atomicAdd(out, s * INV_DEN);
    }
}

}  // namespace

extern "C" void kernel_launch(void* const* d_in, const int* in_sizes, int n_in,
                              void* d_out, int out_size)
{
    const float* noisy = (const float*)d_in[0];
    const float* deno  = (const float*)d_in[1];
    float* out = (float*)d_out;

    init_out_kernel<<<1, 1>>>(out);
    dnls_loss_kernel<<<B_ * Q_, 256>>>(noisy, deno, out);
}

// round 11
// speedup vs baseline: 2.0689x; 1.1676x over previous
#include <cuda_runtime.h>
#include <cstdint>

namespace {

constexpr int B_  = 2;
constexpr int T_  = 5;
constexpr int C_  = 3;
constexpr int H_  = 96;
constexpr int W_  = 96;
constexpr int S0_ = 4;
constexpr int NH_ = H_ / S0_;            // 24
constexpr int NW_ = W_ / S0_;            // 24
constexpr int Q_  = T_ * NH_ * NW_;      // 2880
constexpr int L_  = 243;                 // 3 * 9 * 9
constexpr int K_  = 10;
constexpr int LSELF = 121;
constexpr int HW_   = H_ * W_;
constexpr int CHW_  = C_ * HW_;
constexpr int TCHW_ = T_ * CHW_;
constexpr float INV_DEN = 1.0f / (float)(B_ * Q_ * (K_ - 1));   // 1/51840

constexpr int TR = 15;   // tile rows/cols

__device__ __forceinline__ int refl(int i, int n) {
    i = (i < 0) ? -i : i;
    return (i >= n) ? (2 * (n - 1) - i) : i;
}
__device__ __forceinline__ int clampi(int v, int lo, int hi) {
    return v < lo ? lo : (v > hi ? hi : v);
}
__device__ __forceinline__ unsigned long long umin64(unsigned long long a, unsigned long long b) {
    return a < b ? a : b;
}

__global__ void init_out_kernel(float* out) { out[0] = 0.0f; }

__global__ __launch_bounds__(256, 6)
void dnls_loss_kernel(const float* __restrict__ noisy,
                      const float* __restrict__ deno,
                      float* __restrict__ out)
{
    const int bq = blockIdx.x;
    const int b  = bq / Q_;
    const int q  = bq - b * Q_;
    const int qt = q / (NH_ * NW_);
    const int rem = q - qt * (NH_ * NW_);
    const int qh = (rem / NW_) * S0_;
    const int qw = (rem - (rem / NW_) * NW_) * S0_;

    const int tid = threadIdx.x;

    const float* nb = noisy + (size_t)b * TCHW_;
    const float* db = deno  + (size_t)b * TCHW_;

    // Channel-innermost float4 layout: one LDS.128 per patch position.
    __shared__ float4 tile[3][TR][TR];     // [frame][row][col] -> (c0,c1,c2,pad)
    __shared__ float4 qp4[25];             // query 5x5 positions, rgb in xyz
    __shared__ float4 denoQ4[49];          // deno 7x7 positions, rgb in xyz
    __shared__ unsigned long long keys[256];
    __shared__ int sel_l[K_ - 1];          // ranks 1..9
    __shared__ float wsum[8];

    const int rlo = clampi(qh - 7, 0, H_ - TR);
    const int wlo = clampi(qw - 7, 0, W_ - TR);

    // ---- Stage tile: contiguous crop, fully in-bounds; gather 3 channels per pos ----
    for (int i = tid; i < 3 * TR * TR; i += 256) {
        int f  = i / (TR * TR);
        int r0 = i - f * (TR * TR);
        int r  = r0 / TR;
        int cl = r0 - r * TR;
        int gt = clampi(qt - 1 + f, 0, T_ - 1);
        const float* base = nb + gt * CHW_ + (rlo + r) * W_ + (wlo + cl);
        float4 v;
        v.x = __ldg(base);
        v.y = __ldg(base + HW_);
        v.z = __ldg(base + 2 * HW_);
        v.w = 0.0f;
        tile[f][r][cl] = v;
    }
    if (tid < 25) {
        int ph = tid / 5, pw = tid - (tid / 5) * 5;
        const float* base = nb + qt * CHW_ + refl(qh + ph - 2, H_) * W_ + refl(qw + pw - 2, W_);
        float4 v;
        v.x = __ldg(base);
        v.y = __ldg(base + HW_);
        v.z = __ldg(base + 2 * HW_);
        v.w = 0.0f;
        qp4[tid] = v;
    }
    if (tid >= 32 && tid < 32 + 49) {
        int pos = tid - 32;
        int ph = pos / 7, pw = pos - (pos / 7) * 7;
        const float* base = db + qt * CHW_ + refl(qh + ph - 3, H_) * W_ + refl(qw + pw - 3, W_);
        float4 v;
        v.x = __ldg(base);
        v.y = __ldg(base + HW_);
        v.z = __ldg(base + 2 * HW_);
        v.w = 0.0f;
        denoQ4[pos] = v;
    }
    __syncthreads();

    // ---- Phase A: candidate distances; one LDS.128 pair per patch position ----
    unsigned long long mykey = 0xFFFFFFFFFFFFFFFFULL;
    if (tid < L_ && tid != LSELF) {
        const int dt = tid / 81 - 1;
        const int dh = ((tid / 9) % 9) - 4;
        const int dw = (tid % 9) - 4;
        const int ch = clampi(qh + dh, 0, H_ - 1);
        const int cw = clampi(qw + dw, 0, W_ - 1);
        const int f  = dt + 1;

        int rOff[5], cOff[5];
        #pragma unroll
        for (int p = 0; p < 5; p++) {
            rOff[p] = (refl(ch + p - 2, H_) - rlo) * TR;
            cOff[p] = refl(cw + p - 2, W_) - wlo;
        }

        const float4* tb = &tile[f][0][0];

        float d = 0.0f;
        #pragma unroll
        for (int ph = 0; ph < 5; ph++) {
            #pragma unroll
            for (int pw = 0; pw < 5; pw++) {
                float4 cv = tb[rOff[ph] + cOff[pw]];     // one dynamic LDS.128
                float4 qv = qp4[ph * 5 + pw];            // immediate LDS.128 (broadcast)
                float d0 = qv.x - cv.x;
                float d1 = qv.y - cv.y;
                float d2 = qv.z - cv.z;
                d = fmaf(d0, d0, d);
                d = fmaf(d1, d1, d);
                d = fmaf(d2, d2, d);
            }
        }
        unsigned int fb = __float_as_uint(d);
        fb = (fb & 0x80000000u) ? ~fb : (fb | 0x80000000u);
        mykey = ((unsigned long long)fb << 32) | (unsigned int)tid;
    }
    keys[tid] = mykey;
    __syncthreads();

    // ---- Phase B: warp 0 selects 9 smallest (self rank-0 is implicit) ----
    if (tid < 32) {
        unsigned long long r[8];
        #pragma unroll
        for (int j = 0; j < 8; j++) r[j] = keys[tid + 32 * j];
        #pragma unroll
        for (int k = 0; k < K_ - 1; k++) {
            unsigned long long m = r[0];
            #pragma unroll
            for (int j = 1; j < 8; j++) m = umin64(m, r[j]);
            #pragma unroll
            for (int off = 16; off; off >>= 1)
                m = umin64(m, __shfl_xor_sync(0xFFFFFFFFu, m, off));
            if (tid == 0) sel_l[k] = (int)(m & 0xFFFFFFFFu);
            #pragma unroll
            for (int j = 0; j < 8; j++)
                if (r[j] == m) r[j] = 0xFFFFFFFFFFFFFFFFULL;
        }
    }
    __syncthreads();

    // ---- Phase C: refined 7x7x3 SSD for ranks 1..9 ----
    float acc = 0.0f;
    if (tid < 252) {
        const int kk = tid / 28;                 // neighbor rank 1..9 (index 0..8)
        const int s0 = tid - kk * 28;            // 0..27, strides over 49 positions
        const int l  = sel_l[kk];
        const int dt = l / 81 - 1;
        const int dh = ((l / 9) % 9) - 4;
        const int dw = (l % 9) - 4;
        const int ih = clampi(qh + dh, 0, H_ - 1);
        const int iw = clampi(qw + dw, 0, W_ - 1);
        const int f  = dt + 1;
        const float4* tb = &tile[f][0][0];

        for (int pos = s0; pos < 49; pos += 28) {
            int ph = pos / 7, pw = pos - (pos / 7) * 7;
            int rr = refl(ih + ph - 3, H_) - rlo;
            int cc = refl(iw + pw - 3, W_) - wlo;
            float4 cv = tb[rr * TR + cc];
            float4 qv = denoQ4[pos];
            float d0 = qv.x - cv.x;
            float d1 = qv.y - cv.y;
            float d2 = qv.z - cv.z;
            acc = fmaf(d0, d0, acc);
            acc = fmaf(d1, d1, acc);
            acc = fmaf(d2, d2, acc);
        }
    }

    // ---- Block reduce + one atomic per CTA ----
    #pragma unroll
    for (int off = 16; off; off >>= 1)
        acc += __shfl_down_sync(0xFFFFFFFFu, acc, off);
    if ((tid & 31) == 0) wsum[tid >> 5] = acc;
    __syncthreads();
    if (tid == 0) {
        float s = 0.0f;
        #pragma unroll
        for (int i = 0; i < 8; i++) s += wsum[i];
        atomicAdd(out, s * INV_DEN);
    }
}

}  // namespace

extern "C" void kernel_launch(void* const* d_in, const int* in_sizes, int n_in,
                              void* d_out, int out_size)
{
    const float* noisy = (const float*)d_in[0];
    const float* deno  = (const float*)d_in[1];
    float* out = (float*)d_out;

    init_out_kernel<<<1, 1>>>(out);
    dnls_loss_kernel<<<B_ * Q_, 256>>>(noisy, deno, out);
}

// round 12
// speedup vs baseline: 2.3901x; 1.1552x over previous
#include <cuda_runtime.h>
#include <cstdint>

namespace {

constexpr int B_  = 2;
constexpr int T_  = 5;
constexpr int C_  = 3;
constexpr int H_  = 96;
constexpr int W_  = 96;
constexpr int S0_ = 4;
constexpr int NH_ = H_ / S0_;            // 24
constexpr int NW_ = W_ / S0_;            // 24
constexpr int Q_  = T_ * NH_ * NW_;      // 2880
constexpr int L_  = 243;                 // 3 * 9 * 9
constexpr int K_  = 10;
constexpr int LSELF = 121;
constexpr int HW_   = H_ * W_;
constexpr int CHW_  = C_ * HW_;
constexpr int TCHW_ = T_ * CHW_;
constexpr float INV_DEN = 1.0f / (float)(B_ * Q_ * (K_ - 1));   // 1/51840

constexpr int TR = 15;   // tile rows/cols

__device__ __forceinline__ int refl(int i, int n) {
    i = (i < 0) ? -i : i;
    return (i >= n) ? (2 * (n - 1) - i) : i;
}
__device__ __forceinline__ int clampi(int v, int lo, int hi) {
    return v < lo ? lo : (v > hi ? hi : v);
}
__device__ __forceinline__ unsigned long long umin64(unsigned long long a, unsigned long long b) {
    return a < b ? a : b;
}

__global__ void init_out_kernel(float* out) { out[0] = 0.0f; }

__global__ __launch_bounds__(256, 4)
void dnls_loss_kernel(const float* __restrict__ noisy,
                      const float* __restrict__ deno,
                      float* __restrict__ out)
{
    const int bq = blockIdx.x;
    const int b  = bq / Q_;
    const int q  = bq - b * Q_;
    const int qt = q / (NH_ * NW_);
    const int rem = q - qt * (NH_ * NW_);
    const int qh = (rem / NW_) * S0_;
    const int qw = (rem - (rem / NW_) * NW_) * S0_;

    const int tid = threadIdx.x;

    const float* nb = noisy + (size_t)b * TCHW_;
    const float* db = deno  + (size_t)b * TCHW_;

    __shared__ float4 tile[3][TR][TR];     // [frame][row][col] -> (c0,c1,c2,pad)
    __shared__ float4 qp4[25];             // query 5x5 positions, rgb in xyz
    __shared__ float4 denoQ4[49];          // deno 7x7 positions, rgb in xyz
    __shared__ float  psum[135 * 9];       // per-(f,dh,ph) partial SSDs over 9 dw
    __shared__ unsigned long long keys[256];
    __shared__ int sel_l[K_ - 1];          // ranks 1..9
    __shared__ float wsum[8];

    const int rlo = clampi(qh - 7, 0, H_ - TR);
    const int wlo = clampi(qw - 7, 0, W_ - TR);

    // ---- Stage tile: contiguous crop, fully in-bounds; gather 3 channels per pos ----
    for (int i = tid; i < 3 * TR * TR; i += 256) {
        int f  = i / (TR * TR);
        int r0 = i - f * (TR * TR);
        int r  = r0 / TR;
        int cl = r0 - r * TR;
        int gt = clampi(qt - 1 + f, 0, T_ - 1);
        const float* base = nb + gt * CHW_ + (rlo + r) * W_ + (wlo + cl);
        float4 v;
        v.x = __ldg(base);
        v.y = __ldg(base + HW_);
        v.z = __ldg(base + 2 * HW_);
        v.w = 0.0f;
        tile[f][r][cl] = v;
    }
    if (tid < 25) {
        int ph = tid / 5, pw = tid - (tid / 5) * 5;
        const float* base = nb + qt * CHW_ + refl(qh + ph - 2, H_) * W_ + refl(qw + pw - 2, W_);
        float4 v;
        v.x = __ldg(base);
        v.y = __ldg(base + HW_);
        v.z = __ldg(base + 2 * HW_);
        v.w = 0.0f;
        qp4[tid] = v;
    }
    if (tid >= 32 && tid < 32 + 49) {
        int pos = tid - 32;
        int ph = pos / 7, pw = pos - (pos / 7) * 7;
        const float* base = db + qt * CHW_ + refl(qh + ph - 3, H_) * W_ + refl(qw + pw - 3, W_);
        float4 v;
        v.x = __ldg(base);
        v.y = __ldg(base + HW_);
        v.z = __ldg(base + 2 * HW_);
        v.w = 0.0f;
        denoQ4[pos] = v;
    }
    __syncthreads();

    // ---- Phase A ----
    unsigned long long mykey = 0xFFFFFFFFFFFFFFFFULL;

    const bool fastw = (qw >= 8) && (qw <= 88);   // CTA-uniform: no clamp/reflect in w

    if (fastw) {
        // Shared column-window: item = (f, dh, ph). Each item loads its row's
        // 13 consecutive float4s once; column j serves candidates dw = j-pw.
        if (tid < 135) {
            const int f   = tid / 45;
            const int r0  = tid - f * 45;
            const int dhi = r0 / 5;             // 0..8 (dh = dhi-4)
            const int ph  = r0 - dhi * 5;
            const int ch  = clampi(qh + dhi - 4, 0, H_ - 1);
            const int rr  = refl(ch + ph - 2, H_) - rlo;
            // Column window: global col (qw-6+j) -> tile col (qw-6+j)-wlo = j+1 (wlo=qw-7).
            const float4* row = &tile[f][rr][1];

            float4 q0 = qp4[ph * 5 + 0];
            float4 q1 = qp4[ph * 5 + 1];
            float4 q2 = qp4[ph * 5 + 2];
            float4 q3 = qp4[ph * 5 + 3];
            float4 q4 = qp4[ph * 5 + 4];

            float acc[9];
            #pragma unroll
            for (int k = 0; k < 9; k++) acc[k] = 0.0f;

            #pragma unroll
            for (int j = 0; j < 13; j++) {
                float4 v = row[j];                    // immediate-offset LDS.128
                #pragma unroll
                for (int pw = 0; pw < 5; pw++) {
                    const int dw = j - pw;
                    if (dw >= 0 && dw < 9) {
                        float4 qv = (pw == 0) ? q0 : (pw == 1) ? q1
                                  : (pw == 2) ? q2 : (pw == 3) ? q3 : q4;
                        float d0 = qv.x - v.x;
                        float d1 = qv.y - v.y;
                        float d2 = qv.z - v.z;
                        acc[dw] = fmaf(d0, d0, acc[dw]);
                        acc[dw] = fmaf(d1, d1, acc[dw]);
                        acc[dw] = fmaf(d2, d2, acc[dw]);
                    }
                }
            }
            #pragma unroll
            for (int dw = 0; dw < 9; dw++) psum[tid * 9 + dw] = acc[dw];
        }
        __syncthreads();

        if (tid < L_ && tid != LSELF) {
            const int f   = tid / 81;
            const int dhi = (tid / 9) % 9;
            const int dw  = tid % 9;
            const int base = (f * 45 + dhi * 5) * 9 + dw;
            float d = psum[base] + psum[base + 9] + psum[base + 18]
                    + psum[base + 27] + psum[base + 36];
            unsigned int fb = __float_as_uint(d);
            fb = (fb & 0x80000000u) ? ~fb : (fb | 0x80000000u);
            mykey = ((unsigned long long)fb << 32) | (unsigned int)tid;
        }
    } else {
        // Generic border path: per-candidate direct SSD (round-11 code).
        if (tid < L_ && tid != LSELF) {
            const int dt = tid / 81 - 1;
            const int dh = ((tid / 9) % 9) - 4;
            const int dw = (tid % 9) - 4;
            const int ch = clampi(qh + dh, 0, H_ - 1);
            const int cw = clampi(qw + dw, 0, W_ - 1);
            const int f  = dt + 1;

            int rOff[5], cOff[5];
            #pragma unroll
            for (int p = 0; p < 5; p++) {
                rOff[p] = (refl(ch + p - 2, H_) - rlo) * TR;
                cOff[p] = refl(cw + p - 2, W_) - wlo;
            }

            const float4* tb = &tile[f][0][0];

            float d = 0.0f;
            #pragma unroll
            for (int ph = 0; ph < 5; ph++) {
                #pragma unroll
                for (int pw = 0; pw < 5; pw++) {
                    float4 cv = tb[rOff[ph] + cOff[pw]];
                    float4 qv = qp4[ph * 5 + pw];
                    float d0 = qv.x - cv.x;
                    float d1 = qv.y - cv.y;
                    float d2 = qv.z - cv.z;
                    d = fmaf(d0, d0, d);
                    d = fmaf(d1, d1, d);
                    d = fmaf(d2, d2, d);
                }
            }
            unsigned int fb = __float_as_uint(d);
            fb = (fb & 0x80000000u) ? ~fb : (fb | 0x80000000u);
            mykey = ((unsigned long long)fb << 32) | (unsigned int)tid;
        }
    }
    keys[tid] = mykey;
    __syncthreads();

    // ---- Phase B: warp 0 selects 9 smallest (self rank-0 is implicit) ----
    if (tid < 32) {
        unsigned long long r[8];
        #pragma unroll
        for (int j = 0; j < 8; j++) r[j] = keys[tid + 32 * j];
        #pragma unroll
        for (int k = 0; k < K_ - 1; k++) {
            unsigned long long m = r[0];
            #pragma unroll
            for (int j = 1; j < 8; j++) m = umin64(m, r[j]);
            #pragma unroll
            for (int off = 16; off; off >>= 1)
                m = umin64(m, __shfl_xor_sync(0xFFFFFFFFu, m, off));
            if (tid == 0) sel_l[k] = (int)(m & 0xFFFFFFFFu);
            #pragma unroll
            for (int j = 0; j < 8; j++)
                if (r[j] == m) r[j] = 0xFFFFFFFFFFFFFFFFULL;
        }
    }
    __syncthreads();

    // ---- Phase C: refined 7x7x3 SSD for ranks 1..9 ----
    float acc = 0.0f;
    if (tid < 252) {
        const int kk = tid / 28;                 // neighbor rank 1..9 (index 0..8)
        const int s0 = tid - kk * 28;            // 0..27, strides over 49 positions
        const int l  = sel_l[kk];
        const int dt = l / 81 - 1;
        const int dh = ((l / 9) % 9) - 4;
        const int dw = (l % 9) - 4;
        const int ih = clampi(qh + dh, 0, H_ - 1);
        const int iw = clampi(qw + dw, 0, W_ - 1);
        const int f  = dt + 1;
        const float4* tb = &tile[f][0][0];

        for (int pos = s0; pos < 49; pos += 28) {
            int ph = pos / 7, pw = pos - (pos / 7) * 7;
            int rr = refl(ih + ph - 3, H_) - rlo;
            int cc = refl(iw + pw - 3, W_) - wlo;
            float4 cv = tb[rr * TR + cc];
            float4 qv = denoQ4[pos];
            float d0 = qv.x - cv.x;
            float d1 = qv.y - cv.y;
            float d2 = qv.z - cv.z;
            acc = fmaf(d0, d0, acc);
            acc = fmaf(d1, d1, acc);
            acc = fmaf(d2, d2, acc);
        }
    }

    // ---- Block reduce + one atomic per CTA ----
    #pragma unroll
    for (int off = 16; off; off >>= 1)
        acc += __shfl_down_sync(0xFFFFFFFFu, acc, off);
    if ((tid & 31) == 0) wsum[tid >> 5] = acc;
    __syncthreads();
    if (tid == 0) {
        float s = 0.0f;
        #pragma unroll
        for (int i = 0; i < 8; i++) s += wsum[i];
        atomicAdd(out, s * INV_DEN);
    }
}

}  // namespace

extern "C" void kernel_launch(void* const* d_in, const int* in_sizes, int n_in,
                              void* d_out, int out_size)
{
    const float* noisy = (const float*)d_in[0];
    const float* deno  = (const float*)d_in[1];
    float* out = (float*)d_out;

    init_out_kernel<<<1, 1>>>(out);
    dnls_loss_kernel<<<B_ * Q_, 256>>>(noisy, deno, out);
}

// round 17
// speedup vs baseline: 2.5823x; 1.0804x over previous
#include <cuda_runtime.h>
#include <cstdint>

namespace {

constexpr int B_  = 2;
constexpr int T_  = 5;
constexpr int C_  = 3;
constexpr int H_  = 96;
constexpr int W_  = 96;
constexpr int S0_ = 4;
constexpr int NH_ = H_ / S0_;            // 24
constexpr int NW_ = W_ / S0_;            // 24
constexpr int Q_  = T_ * NH_ * NW_;      // 2880
constexpr int L_  = 243;                 // 3 * 9 * 9
constexpr int K_  = 10;
constexpr int LSELF = 121;
constexpr int HW_   = H_ * W_;
constexpr int CHW_  = C_ * HW_;
constexpr int TCHW_ = T_ * CHW_;
constexpr float INV_DEN = 1.0f / (float)(B_ * Q_ * (K_ - 1));   // 1/51840

constexpr int TR = 15;   // tile rows/cols

__device__ __forceinline__ int refl(int i, int n) {
    i = (i < 0) ? -i : i;
    return (i >= n) ? (2 * (n - 1) - i) : i;
}
__device__ __forceinline__ int clampi(int v, int lo, int hi) {
    return v < lo ? lo : (v > hi ? hi : v);
}
__device__ __forceinline__ unsigned long long umin64(unsigned long long a, unsigned long long b) {
    return a < b ? a : b;
}

__global__ __launch_bounds__(256, 5)
void dnls_loss_kernel(const float* __restrict__ noisy,
                      const float* __restrict__ deno,
                      float* __restrict__ out)
{
    const int bq = blockIdx.x;
    const int b  = bq / Q_;
    const int q  = bq - b * Q_;
    const int qt = q / (NH_ * NW_);
    const int rem = q - qt * (NH_ * NW_);
    const int qh = (rem / NW_) * S0_;
    const int qw = (rem - (rem / NW_) * NW_) * S0_;

    const int tid = threadIdx.x;

    const float* nb = noisy + (size_t)b * TCHW_;
    const float* db = deno  + (size_t)b * TCHW_;

    __shared__ float4 tile[3][TR][TR];     // [frame][row][col] -> (c0,c1,c2,pad)
    __shared__ float4 qp4[25];             // query 5x5 positions, rgb in xyz
    __shared__ float4 denoQ4[49];          // deno 7x7 positions, rgb in xyz
    __shared__ float  psum[135 * 9];       // per-(f,dh,ph) partial SSDs over 9 dw
    __shared__ unsigned long long keys[256];
    __shared__ int sel_l[K_ - 1];          // ranks 1..9
    __shared__ float wsum[8];

    const int rlo = clampi(qh - 7, 0, H_ - TR);
    const int wlo = clampi(qw - 7, 0, W_ - TR);

    // ---- Stage tile: contiguous crop, fully in-bounds; gather 3 channels per pos ----
    for (int i = tid; i < 3 * TR * TR; i += 256) {
        int f  = i / (TR * TR);
        int r0 = i - f * (TR * TR);
        int r  = r0 / TR;
        int cl = r0 - r * TR;
        int gt = clampi(qt - 1 + f, 0, T_ - 1);
        const float* base = nb + gt * CHW_ + (rlo + r) * W_ + (wlo + cl);
        float4 v;
        v.x = __ldg(base);
        v.y = __ldg(base + HW_);
        v.z = __ldg(base + 2 * HW_);
        v.w = 0.0f;
        tile[f][r][cl] = v;
    }
    if (tid < 25) {
        int ph = tid / 5, pw = tid - (tid / 5) * 5;
        const float* base = nb + qt * CHW_ + refl(qh + ph - 2, H_) * W_ + refl(qw + pw - 2, W_);
        float4 v;
        v.x = __ldg(base);
        v.y = __ldg(base + HW_);
        v.z = __ldg(base + 2 * HW_);
        v.w = 0.0f;
        qp4[tid] = v;
    }
    if (tid >= 32 && tid < 32 + 49) {
        int pos = tid - 32;
        int ph = pos / 7, pw = pos - (pos / 7) * 7;
        const float* base = db + qt * CHW_ + refl(qh + ph - 3, H_) * W_ + refl(qw + pw - 3, W_);
        float4 v;
        v.x = __ldg(base);
        v.y = __ldg(base + HW_);
        v.z = __ldg(base + 2 * HW_);
        v.w = 0.0f;
        denoQ4[pos] = v;
    }
    __syncthreads();

    // ---- Phase A ----
    unsigned long long mykey = 0xFFFFFFFFFFFFFFFFULL;

    const bool fastw = (qw >= 8) && (qw <= 88);   // CTA-uniform: no clamp/reflect in w

    if (fastw) {
        // Shared column-window: item = (f, dh, ph). Each item loads its row's
        // 13 consecutive float4s once; column j serves candidates dw = j-pw.
        if (tid < 135) {
            const int f   = tid / 45;
            const int r0  = tid - f * 45;
            const int dhi = r0 / 5;             // 0..8 (dh = dhi-4)
            const int ph  = r0 - dhi * 5;
            const int ch  = clampi(qh + dhi - 4, 0, H_ - 1);
            const int rr  = refl(ch + ph - 2, H_) - rlo;
            // Column window: global col (qw-6+j) -> tile col (qw-6+j)-wlo = j+1 (wlo=qw-7).
            const float4* row = &tile[f][rr][1];

            // Query row as 15 scalars (drop dead .w lanes; saves registers).
            float qr[15];
            #pragma unroll
            for (int pw = 0; pw < 5; pw++) {
                float4 qv = qp4[ph * 5 + pw];
                qr[pw * 3 + 0] = qv.x;
                qr[pw * 3 + 1] = qv.y;
                qr[pw * 3 + 2] = qv.z;
            }

            float acc[9];
            #pragma unroll
            for (int k = 0; k < 9; k++) acc[k] = 0.0f;

            #pragma unroll
            for (int j = 0; j < 13; j++) {
                float4 v = row[j];                    // immediate-offset LDS.128
                #pragma unroll
                for (int pw = 0; pw < 5; pw++) {
                    const int dw = j - pw;
                    if (dw >= 0 && dw < 9) {
                        float d0 = qr[pw * 3 + 0] - v.x;
                        float d1 = qr[pw * 3 + 1] - v.y;
                        float d2 = qr[pw * 3 + 2] - v.z;
                        acc[dw] = fmaf(d0, d0, acc[dw]);
                        acc[dw] = fmaf(d1, d1, acc[dw]);
                        acc[dw] = fmaf(d2, d2, acc[dw]);
                    }
                }
            }
            #pragma unroll
            for (int dw = 0; dw < 9; dw++) psum[tid * 9 + dw] = acc[dw];
        }
        __syncthreads();

        if (tid < L_ && tid != LSELF) {
            const int f   = tid / 81;
            const int dhi = (tid / 9) % 9;
            const int dw  = tid % 9;
            const int base = (f * 45 + dhi * 5) * 9 + dw;
            float d = psum[base] + psum[base + 9] + psum[base + 18]
                    + psum[base + 27] + psum[base + 36];
            unsigned int fb = __float_as_uint(d);
            fb = (fb & 0x80000000u) ? ~fb : (fb | 0x80000000u);
            mykey = ((unsigned long long)fb << 32) | (unsigned int)tid;
        }
    } else {
        // Generic border path: per-candidate direct SSD.
        if (tid < L_ && tid != LSELF) {
            const int dt = tid / 81 - 1;
            const int dh = ((tid / 9) % 9) - 4;
            const int dw = (tid % 9) - 4;
            const int ch = clampi(qh + dh, 0, H_ - 1);
            const int cw = clampi(qw + dw, 0, W_ - 1);
            const int f  = dt + 1;

            int rOff[5], cOff[5];
            #pragma unroll
            for (int p = 0; p < 5; p++) {
                rOff[p] = (refl(ch + p - 2, H_) - rlo) * TR;
                cOff[p] = refl(cw + p - 2, W_) - wlo;
            }

            const float4* tb = &tile[f][0][0];

            float d = 0.0f;
            #pragma unroll
            for (int ph = 0; ph < 5; ph++) {
                #pragma unroll
                for (int pw = 0; pw < 5; pw++) {
                    float4 cv = tb[rOff[ph] + cOff[pw]];
                    float4 qv = qp4[ph * 5 + pw];
                    float d0 = qv.x - cv.x;
                    float d1 = qv.y - cv.y;
                    float d2 = qv.z - cv.z;
                    d = fmaf(d0, d0, d);
                    d = fmaf(d1, d1, d);
                    d = fmaf(d2, d2, d);
                }
            }
            unsigned int fb = __float_as_uint(d);
            fb = (fb & 0x80000000u) ? ~fb : (fb | 0x80000000u);
            mykey = ((unsigned long long)fb << 32) | (unsigned int)tid;
        }
    }
    keys[tid] = mykey;
    __syncthreads();

    // ---- Phase B: warp 0 selects 9 smallest (self rank-0 is implicit) ----
    if (tid < 32) {
        unsigned long long r[8];
        #pragma unroll
        for (int j = 0; j < 8; j++) r[j] = keys[tid + 32 * j];
        #pragma unroll
        for (int k = 0; k < K_ - 1; k++) {
            unsigned long long m = r[0];
            #pragma unroll
            for (int j = 1; j < 8; j++) m = umin64(m, r[j]);
            #pragma unroll
            for (int off = 16; off; off >>= 1)
                m = umin64(m, __shfl_xor_sync(0xFFFFFFFFu, m, off));
            if (tid == 0) sel_l[k] = (int)(m & 0xFFFFFFFFu);
            #pragma unroll
            for (int j = 0; j < 8; j++)
                if (r[j] == m) r[j] = 0xFFFFFFFFFFFFFFFFULL;
        }
    }
    __syncthreads();

    // ---- Phase C: refined 7x7x3 SSD for ranks 1..9 ----
    float acc = 0.0f;
    if (tid < 252) {
        const int kk = tid / 28;                 // neighbor rank 1..9 (index 0..8)
        const int s0 = tid - kk * 28;            // 0..27, strides over 49 positions
        const int l  = sel_l[kk];
        const int dt = l / 81 - 1;
        const int dh = ((l / 9) % 9) - 4;
        const int dw = (l % 9) - 4;
        const int ih = clampi(qh + dh, 0, H_ - 1);
        const int iw = clampi(qw + dw, 0, W_ - 1);
        const int f  = dt + 1;
        const float4* tb = &tile[f][0][0];

        for (int pos = s0; pos < 49; pos += 28) {
            int ph = pos / 7, pw = pos - (pos / 7) * 7;
            int rr = refl(ih + ph - 3, H_) - rlo;
            int cc = refl(iw + pw - 3, W_) - wlo;
            float4 cv = tb[rr * TR + cc];
            float4 qv = denoQ4[pos];
            float d0 = qv.x - cv.x;
            float d1 = qv.y - cv.y;
            float d2 = qv.z - cv.z;
            acc = fmaf(d0, d0, acc);
            acc = fmaf(d1, d1, acc);
            acc = fmaf(d2, d2, acc);
        }
    }

    // ---- Block reduce + one atomic per CTA ----
    #pragma unroll
    for (int off = 16; off; off >>= 1)
        acc += __shfl_down_sync(0xFFFFFFFFu, acc, off);
    if ((tid & 31) == 0) wsum[tid >> 5] = acc;
    __syncthreads();
    if (tid == 0) {
        float s = 0.0f;
        #pragma unroll
        for (int i = 0; i < 8; i++) s += wsum[i];
        atomicAdd(out, s * INV_DEN);
    }
}

}  // namespace

extern "C" void kernel_launch(void* const* d_in, const int* in_sizes, int n_in,
                              void* d_out, int out_size)
{
    const float* noisy = (const float*)d_in[0];
    const float* deno  = (const float*)d_in[1];
    float* out = (float*)d_out;

    // Zero the scalar accumulator (graph-capturable; bitwise 0 == 0.0f).
    cudaMemsetAsync(out, 0, sizeof(float));
    dnls_loss_kernel<<<B_ * Q_, 256>>>(noisy, deno, out);
}